// round 15
// baseline (speedup 1.0000x reference)
#include <cuda_runtime.h>

// ExponentialUnitNorm: exact segmented chunked linear-scan — occupancy-3 probe.
// Identical phase structure to the converged TCK=8 kernel; TCK reduced to 6 so
// the live set fits 42 regs and 3 blocks/SM become resident (48 warps/SM).
// x: [B=16, C=1, T=2000, F=481, 2] fp32.
// s_t = 0.01*m_t + 0.99*s_{t-1}; out = x/sqrt(s).
// Chunk of length L from zero state: s_u = 0.99^(u+1)*s_in + p_u; A_L = 0.99^L.
// T = 20 segments * (16 chunks * 6) + 1 tail segment * (16 chunks * 5) = 1920 + 80.
//
// Block: 512 threads = 32 f-lanes x 16 chunk-warps. Grid: 16 b x 16 f-tiles = 256.

#define B_DIM 16
#define T_DIM 2000
#define F_DIM 481
#define CH    16
#define TCK   6
#define SEGSZ (CH * TCK)       // 96
#define NSEGM 20               // 20*96 = 1920
#define AL 0.99f
#define BE 0.01f

__global__ __launch_bounds__(512, 3)
void eun_kernel(const float2* __restrict__ x,
                const float* __restrict__ init_state,
                float2* __restrict__ out) {
    __shared__ float Bs[2][CH][32];

    const int tid   = threadIdx.x;
    const int lane  = tid & 31;
    const int chunk = tid >> 5;              // 0..15
    const int ftile = blockIdx.x & 15;
    const int b     = blockIdx.x >> 4;
    const int fraw  = ftile * 32 + lane;
    const bool act  = (fraw < F_DIM);
    const int f     = act ? fraw : (F_DIM - 1);   // clamp: loads always valid

    // 0.99^(u+1), u = 0..5 (become FFMA immediates — zero register cost)
    const float POW[TCK] = {0.99f, 0.9801f, 0.970299f,
                            0.96059601f, 0.95099005f, 0.94148015f};
    const float A6 = 0.94148015f;            // 0.99^6
    const float A5 = 0.95099005f;            // 0.99^5

    float scarry = init_state[f];

    const float2* __restrict__ xbase = x   + (size_t)b * T_DIM * F_DIM + f;
    float2* __restrict__       obase = out + (size_t)b * T_DIM * F_DIM + f;

    float2 v[TCK], vn[TCK];

    // Prologue: load segment 0 — unconditional.
    {
        const int off = chunk * TCK * F_DIM;
        #pragma unroll
        for (int u = 0; u < TCK; ++u)
            v[u] = __ldg(xbase + off + u * F_DIM);
    }

    #pragma unroll 1
    for (int seg = 0; seg < NSEGM; ++seg) {
        const int par   = seg & 1;
        const int start = seg * SEGSZ;

        // ---- prefix within chunk (zero initial state) ----
        float p[TCK];
        float pc = 0.0f;
        #pragma unroll
        for (int u = 0; u < TCK; ++u) {
            float m2 = fmaf(v[u].x, v[u].x, v[u].y * v[u].y);
            m2 = fmaxf(m2, 1e-14f);
            float m;
            asm("sqrt.approx.f32 %0, %1;" : "=f"(m) : "f"(m2));
            pc = fmaf(AL, pc, BE * m);
            p[u] = pc;
        }
        Bs[par][chunk][lane] = pc;

        // ---- prefetch next segment BEFORE barrier (latency overlap) ----
        if (seg < NSEGM - 1) {
            const int noff = (start + SEGSZ + chunk * TCK) * F_DIM;
            #pragma unroll
            for (int u = 0; u < TCK; ++u)
                vn[u] = __ldg(xbase + noff + u * F_DIM);
        } else {
            const int noff = (NSEGM * SEGSZ + chunk * 5) * F_DIM;
            #pragma unroll
            for (int u = 0; u < 5; ++u)
                vn[u] = __ldg(xbase + noff + u * F_DIM);
        }

        __syncthreads();

        // ---- per-warp redundant compose over all CH chunks ----
        float s = scarry;
        float mystart = s;
        #pragma unroll
        for (int c = 0; c < CH; ++c) {
            if (c == chunk) mystart = s;
            s = fmaf(A6, s, Bs[par][c][lane]);
        }
        scarry = s;

        // ---- parallel rescale; store predicated on act only ----
        {
            const int ooff = (start + chunk * TCK) * F_DIM;
            #pragma unroll
            for (int u = 0; u < TCK; ++u) {
                float st = fmaf(POW[u], mystart, p[u]);
                float r;
                asm("rsqrt.approx.f32 %0, %1;" : "=f"(r) : "f"(st));
                float2 w;
                w.x = v[u].x * r;
                w.y = v[u].y * r;
                if (act) obase[ooff + u * F_DIM] = w;
            }
            #pragma unroll
            for (int u = 0; u < TCK; ++u)
                v[u] = vn[u];
        }
    }

    // ---- tail segment: TCK=5 (t in [1920, 2000)) ----
    {
        const int start = NSEGM * SEGSZ;     // 1920
        float p[5];
        float pc = 0.0f;
        #pragma unroll
        for (int u = 0; u < 5; ++u) {
            float m2 = fmaf(v[u].x, v[u].x, v[u].y * v[u].y);
            m2 = fmaxf(m2, 1e-14f);
            float m;
            asm("sqrt.approx.f32 %0, %1;" : "=f"(m) : "f"(m2));
            pc = fmaf(AL, pc, BE * m);
            p[u] = pc;
        }
        // Last main segment (seg 19) used parity 1; its Bs[1] readers passed
        // barrier 19, which this write follows -> parity 0 buffer is free, but
        // parity 1 is also safe. Use parity 0 (last written at seg 18, consumed
        // before barrier 19).
        Bs[0][chunk][lane] = pc;
        __syncthreads();

        float s = scarry;
        float mystart = s;
        #pragma unroll
        for (int c = 0; c < CH; ++c) {
            if (c == chunk) mystart = s;
            s = fmaf(A5, s, Bs[0][c][lane]);
        }

        {
            const int ooff = (start + chunk * 5) * F_DIM;
            #pragma unroll
            for (int u = 0; u < 5; ++u) {
                float st = fmaf(POW[u], mystart, p[u]);
                float r;
                asm("rsqrt.approx.f32 %0, %1;" : "=f"(r) : "f"(st));
                float2 w;
                w.x = v[u].x * r;
                w.y = v[u].y * r;
                if (act) obase[ooff + u * F_DIM] = w;
            }
        }
    }
}

extern "C" void kernel_launch(void* const* d_in, const int* in_sizes, int n_in,
                              void* d_out, int out_size) {
    const float2* x = (const float2*)d_in[0];          // [16,1,2000,481,2] fp32
    const float*  init_state = (const float*)d_in[1];  // [1,1,481,1] fp32
    float2* out = (float2*)d_out;

    dim3 block(512);
    dim3 grid(B_DIM * 16);   // 256 blocks: 16 b x 16 f-tiles
    eun_kernel<<<grid, block>>>(x, init_state, out);
}

// round 16
// speedup vs baseline: 1.4014x; 1.4014x over previous
#include <cuda_runtime.h>

// ExponentialUnitNorm — FINAL CONVERGED KERNEL (verbatim revert of best body).
// Best measured: wall 45.5us, ncu 39.6us, DRAM 62%, 3.0x over first passing kernel.
//
// Exact segmented chunked linear-scan, register-resident, software-pipelined
// loads, single barrier per segment, TCK=8 main segments, clamped-f
// (unconditional loads/compute, predicated stores only).
//
// x: [B=16, C=1, T=2000, F=481, 2] fp32.
// s_t = 0.01*m_t + 0.99*s_{t-1}; out = x/sqrt(s).
// Chunk of length L from zero state: s_u = 0.99^(u+1)*s_in + p_u; A_L = 0.99^L.
// T = 15 segments * (16 chunks * 8) + 1 segment * (16 chunks * 5) = 1920 + 80.
//
// Block: 512 threads = 32 f-lanes x 16 chunk-warps. Grid: 16 b x 16 f-tiles = 256.
//
// Convergence evidence (0-for-4 on perturbations):
//  R7  full unroll + .cs stores        -> +4us
//  R8  prefetch-at-top + stcs          -> +8us
//  R9  ping-pong unroll-by-2           -> +2us
//  R14 TCK=6 / 42-reg occupancy probe  -> +18us; PROVED (a) occupancy is
//      grid-limited (regs 40, occ unchanged), (b) DRAM BW ~ per-thread MLP
//      (8->6 loads cost 30% BW). TCK=8 @ 64 regs / 2 blocks/SM is pinned on
//      both sides. This body reproduced 4x within 0.3us. Do not perturb.

#define B_DIM 16
#define T_DIM 2000
#define F_DIM 481
#define CH    16
#define NSEG8 15
#define AL 0.99f
#define BE 0.01f

__global__ __launch_bounds__(512, 2)
void eun_kernel(const float2* __restrict__ x,
                const float* __restrict__ init_state,
                float2* __restrict__ out) {
    __shared__ float Bs[2][CH][32];

    const int tid   = threadIdx.x;
    const int lane  = tid & 31;
    const int chunk = tid >> 5;              // 0..15
    const int ftile = blockIdx.x & 15;
    const int b     = blockIdx.x >> 4;
    const int fraw  = ftile * 32 + lane;
    const bool act  = (fraw < F_DIM);
    const int f     = act ? fraw : (F_DIM - 1);   // clamp: loads always valid (broadcast)

    // 0.99^(u+1), u = 0..7
    const float POW[8] = {0.99f, 0.9801f, 0.970299f, 0.96059601f,
                          0.95099005f, 0.94148015f, 0.93206535f, 0.92274469f};
    const float A8 = 0.92274469f;            // 0.99^8
    const float A5 = 0.95099005f;            // 0.99^5

    float scarry = init_state[f];

    const float2* __restrict__ xbase = x   + (size_t)b * T_DIM * F_DIM + f;
    float2* __restrict__       obase = out + (size_t)b * T_DIM * F_DIM + f;

    float2 v[8], vn[8];

    // Prologue: load segment 0 (TCK=8) — unconditional.
    {
        const int off = chunk * 8 * F_DIM;
        #pragma unroll
        for (int u = 0; u < 8; ++u)
            v[u] = __ldg(xbase + off + u * F_DIM);
    }

    #pragma unroll 1
    for (int seg = 0; seg < NSEG8; ++seg) {
        const int par   = seg & 1;
        const int start = seg * (CH * 8);

        // ---- prefix within chunk (zero initial state) ----
        float p[8];
        float pc = 0.0f;
        #pragma unroll
        for (int u = 0; u < 8; ++u) {
            float m2 = fmaf(v[u].x, v[u].x, v[u].y * v[u].y);
            m2 = fmaxf(m2, 1e-14f);
            float m;
            asm("sqrt.approx.f32 %0, %1;" : "=f"(m) : "f"(m2));
            pc = fmaf(AL, pc, BE * m);
            p[u] = pc;
        }
        Bs[par][chunk][lane] = pc;

        // ---- prefetch next segment BEFORE barrier (latency overlap) ----
        if (seg < NSEG8 - 1) {
            const int noff = (start + CH * 8 + chunk * 8) * F_DIM;
            #pragma unroll
            for (int u = 0; u < 8; ++u)
                vn[u] = __ldg(xbase + noff + u * F_DIM);
        } else {
            const int noff = (NSEG8 * CH * 8 + chunk * 5) * F_DIM;
            #pragma unroll
            for (int u = 0; u < 5; ++u)
                vn[u] = __ldg(xbase + noff + u * F_DIM);
        }

        __syncthreads();

        // ---- per-warp redundant compose over all CH chunks ----
        float s = scarry;
        float mystart = s;
        #pragma unroll
        for (int c = 0; c < CH; ++c) {
            if (c == chunk) mystart = s;
            s = fmaf(A8, s, Bs[par][c][lane]);
        }
        scarry = s;

        // ---- parallel rescale; store predicated on act only ----
        {
            const int ooff = (start + chunk * 8) * F_DIM;
            #pragma unroll
            for (int u = 0; u < 8; ++u) {
                float st = fmaf(POW[u], mystart, p[u]);
                float r;
                asm("rsqrt.approx.f32 %0, %1;" : "=f"(r) : "f"(st));
                float2 w;
                w.x = v[u].x * r;
                w.y = v[u].y * r;
                if (act) obase[ooff + u * F_DIM] = w;
            }
            #pragma unroll
            for (int u = 0; u < 8; ++u)
                v[u] = vn[u];
        }
    }

    // ---- tail segment: TCK=5 (t in [1920, 2000)) ----
    {
        const int start = NSEG8 * CH * 8;    // 1920
        float p[5];
        float pc = 0.0f;
        #pragma unroll
        for (int u = 0; u < 5; ++u) {
            float m2 = fmaf(v[u].x, v[u].x, v[u].y * v[u].y);
            m2 = fmaxf(m2, 1e-14f);
            float m;
            asm("sqrt.approx.f32 %0, %1;" : "=f"(m) : "f"(m2));
            pc = fmaf(AL, pc, BE * m);
            p[u] = pc;
        }
        Bs[1][chunk][lane] = pc;             // parity 1: last reader passed barrier 14
        __syncthreads();

        float s = scarry;
        float mystart = s;
        #pragma unroll
        for (int c = 0; c < CH; ++c) {
            if (c == chunk) mystart = s;
            s = fmaf(A5, s, Bs[1][c][lane]);
        }

        {
            const int ooff = (start + chunk * 5) * F_DIM;
            #pragma unroll
            for (int u = 0; u < 5; ++u) {
                float st = fmaf(POW[u], mystart, p[u]);
                float r;
                asm("rsqrt.approx.f32 %0, %1;" : "=f"(r) : "f"(st));
                float2 w;
                w.x = v[u].x * r;
                w.y = v[u].y * r;
                if (act) obase[ooff + u * F_DIM] = w;
            }
        }
    }
}

extern "C" void kernel_launch(void* const* d_in, const int* in_sizes, int n_in,
                              void* d_out, int out_size) {
    const float2* x = (const float2*)d_in[0];          // [16,1,2000,481,2] fp32
    const float*  init_state = (const float*)d_in[1];  // [1,1,481,1] fp32
    float2* out = (float2*)d_out;

    dim3 block(512);
    dim3 grid(B_DIM * 16);   // 256 blocks: 16 b x 16 f-tiles
    eun_kernel<<<grid, block>>>(x, init_state, out);
}